// round 1
// baseline (speedup 1.0000x reference)
#include <cuda_runtime.h>

// 16k -> 24k polyphase resampler (torchaudio/kaldi defaults).
// in_unit=2, out_unit=3 phases, first_indices={-6,-5,-4}, W=13 taps.
// out[c, 3u+i] = sum_j x[c, first[i] + 2u + j] * w[i][j]  (zero-padded x)

#define C_CH    8
#define NPHASE  3
#define WTAPS   13
#define OUT_PT  12   // outputs per thread (4 units x 3 phases)

__global__ __launch_bounds__(256) void resample_16_24_kernel(
    const float* __restrict__ x, const float* __restrict__ wgt,
    float* __restrict__ out, int L, int tot)
{
    const int c = blockIdx.y;
    const long long t  = (long long)blockIdx.x * blockDim.x + threadIdx.x;
    const long long n0 = t * OUT_PT;
    if (n0 >= tot) return;

    const float* xc = x + (size_t)c * (size_t)L;

    // Hoist filter bank into registers (uniform -> L1 broadcast hits)
    float w[NPHASE][WTAPS];
#pragma unroll
    for (int i = 0; i < NPHASE; i++)
#pragma unroll
        for (int j = 0; j < WTAPS; j++)
            w[i][j] = __ldg(&wgt[i * WTAPS + j]);

    // Input window for this thread: global indices [8t-8, 8t+15]
    // (needed range is [8t-6, 8t+14]; padded to 16B alignment)
    const long long g0 = 8 * t - 8;
    float xin[24];
    if (g0 >= 0 && g0 + 24 <= (long long)L) {
        const float4* p = reinterpret_cast<const float4*>(xc + g0);
#pragma unroll
        for (int q = 0; q < 6; q++) {
            float4 v = p[q];
            xin[4*q+0] = v.x; xin[4*q+1] = v.y;
            xin[4*q+2] = v.z; xin[4*q+3] = v.w;
        }
    } else {
        // boundary threads: guarded scalar loads with zero padding
#pragma unroll
        for (int q = 0; q < 24; q++) {
            long long g = g0 + q;
            xin[q] = (g >= 0 && g < (long long)L) ? xc[g] : 0.0f;
        }
    }

    // 12 outputs: n = n0 + 3u + i, input offset within xin = (2+i) + 2u + j
    float o[OUT_PT];
#pragma unroll
    for (int u = 0; u < 4; u++) {
#pragma unroll
        for (int i = 0; i < NPHASE; i++) {
            const int base = 2 + i + 2 * u;
            float s = 0.0f;
#pragma unroll
            for (int j = 0; j < WTAPS; j++)
                s = fmaf(xin[base + j], w[i][j], s);
            o[3 * u + i] = s;
        }
    }

    float* oc = out + (size_t)c * (size_t)tot + n0;
    if (n0 + OUT_PT <= (long long)tot) {
        float4* po = reinterpret_cast<float4*>(oc);
        po[0] = make_float4(o[0], o[1], o[2],  o[3]);
        po[1] = make_float4(o[4], o[5], o[6],  o[7]);
        po[2] = make_float4(o[8], o[9], o[10], o[11]);
    } else {
#pragma unroll
        for (int q = 0; q < OUT_PT; q++)
            if (n0 + q < (long long)tot) oc[q] = o[q];
    }
}

extern "C" void kernel_launch(void* const* d_in, const int* in_sizes, int n_in,
                              void* d_out, int out_size)
{
    const float* x   = (const float*)d_in[0];
    const float* wgt = (const float*)d_in[1];
    float* out = (float*)d_out;

    const int L   = in_sizes[0] / C_CH;   // 4,000,000
    const int tot = out_size   / C_CH;    // 6,000,000

    const long long threads_per_ch = ((long long)tot + OUT_PT - 1) / OUT_PT;
    const int block = 256;
    const int bx = (int)((threads_per_ch + block - 1) / block);
    dim3 grid(bx, C_CH);
    resample_16_24_kernel<<<grid, block>>>(x, wgt, out, L, tot);
}